// round 2
// baseline (speedup 1.0000x reference)
#include <cuda_runtime.h>
#include <math.h>

#define B_ROWS 2048
#define N_ROWS 4096
#define D 256
#define SCALE 2.0f   // 1 / TEMPERATURE

// Scratch (allocation-free: __device__ globals)
__device__ float g_z[N_ROWS * D];     // normalized rows, 4 MB
__device__ float g_rowsum[N_ROWS];    // sum_j!=i exp(sim_ij)
__device__ float g_pos[N_ROWS];       // sim_{i, pos(i)}

// ---------------------------------------------------------------------------
// Kernel 1: L2-normalize each row of concat(z_i, z_j); zero accumulators.
// grid = N_ROWS blocks, 64 threads (each thread owns one float4 of the row).
// ---------------------------------------------------------------------------
__global__ void normalize_kernel(const float* __restrict__ zi,
                                 const float* __restrict__ zj) {
    int r = blockIdx.x;
    int t = threadIdx.x;  // 0..63
    const float* src = (r < B_ROWS) ? (zi + (size_t)r * D)
                                    : (zj + (size_t)(r - B_ROWS) * D);
    float4 v = ((const float4*)src)[t];
    float ss = v.x * v.x + v.y * v.y + v.z * v.z + v.w * v.w;
    #pragma unroll
    for (int m = 16; m; m >>= 1) ss += __shfl_xor_sync(0xffffffffu, ss, m);
    __shared__ float sh[2];
    if ((t & 31) == 0) sh[t >> 5] = ss;
    __syncthreads();
    float tot = sh[0] + sh[1];
    float inv = 1.0f / fmaxf(sqrtf(tot), 1e-12f);
    float4 o = make_float4(v.x * inv, v.y * inv, v.z * inv, v.w * inv);
    ((float4*)(g_z + (size_t)r * D))[t] = o;
    if (t == 0) {
        g_rowsum[r] = 0.0f;
        g_pos[r] = 0.0f;
    }
}

// ---------------------------------------------------------------------------
// Kernel 2: fused sim + exp + row reduction.
// Block computes a 64-row i-tile against a 1024-col j-chunk (16 j-tiles of 64).
// Shared tiles stored transposed [k][row] so compute-loop LDS.128 are
// conflict-free. 256 threads as 16x16, each does a 4x4 micro-tile.
// ---------------------------------------------------------------------------
#define TM 64
#define TN 64
#define KC 64

__global__ __launch_bounds__(256) void sim_kernel() {
    __shared__ float As[KC][TM];
    __shared__ float Bs[KC][TN];

    const int i0    = blockIdx.x * TM;
    const int jbase = blockIdx.y * 1024;
    const int tid   = threadIdx.x;
    const int tx    = tid & 15;   // j sub-tile
    const int ty    = tid >> 4;   // i sub-tile

    float rs[4] = {0.f, 0.f, 0.f, 0.f};

    for (int jt = 0; jt < 16; jt++) {
        const int j0 = jbase + jt * TN;
        float acc[4][4] = {};

        for (int kc = 0; kc < 4; kc++) {
            __syncthreads();  // previous tile's reads done before overwrite
            // Cooperative load: 64 rows x 16 float4 each, for A and B tiles.
            #pragma unroll
            for (int it = 0; it < 4; it++) {
                int idx = it * 256 + tid;
                int row = idx >> 4;      // 0..63
                int k4  = idx & 15;      // 0..15
                float4 a = *(const float4*)&g_z[(size_t)(i0 + row) * D + kc * KC + k4 * 4];
                As[k4 * 4 + 0][row] = a.x;
                As[k4 * 4 + 1][row] = a.y;
                As[k4 * 4 + 2][row] = a.z;
                As[k4 * 4 + 3][row] = a.w;
                float4 b = *(const float4*)&g_z[(size_t)(j0 + row) * D + kc * KC + k4 * 4];
                Bs[k4 * 4 + 0][row] = b.x;
                Bs[k4 * 4 + 1][row] = b.y;
                Bs[k4 * 4 + 2][row] = b.z;
                Bs[k4 * 4 + 3][row] = b.w;
            }
            __syncthreads();

            #pragma unroll
            for (int k = 0; k < KC; k++) {
                float4 a = *(const float4*)&As[k][ty * 4];
                float4 b = *(const float4*)&Bs[k][tx * 4];
                acc[0][0] += a.x * b.x; acc[0][1] += a.x * b.y;
                acc[0][2] += a.x * b.z; acc[0][3] += a.x * b.w;
                acc[1][0] += a.y * b.x; acc[1][1] += a.y * b.y;
                acc[1][2] += a.y * b.z; acc[1][3] += a.y * b.w;
                acc[2][0] += a.z * b.x; acc[2][1] += a.z * b.y;
                acc[2][2] += a.z * b.z; acc[2][3] += a.z * b.w;
                acc[3][0] += a.w * b.x; acc[3][1] += a.w * b.y;
                acc[3][2] += a.w * b.z; acc[3][3] += a.w * b.w;
            }
        }

        // Epilogue for this j-tile: exp, diagonal exclusion, positive capture.
        #pragma unroll
        for (int ii = 0; ii < 4; ii++) {
            int i    = i0 + ty * 4 + ii;
            int posj = (i + B_ROWS) & (N_ROWS - 1);
            #pragma unroll
            for (int jj = 0; jj < 4; jj++) {
                int j   = j0 + tx * 4 + jj;
                float s = SCALE * acc[ii][jj];
                float e = __expf(s);
                if (j != i)    rs[ii] += e;      // negative_sim = sum - diag
                if (j == posj) g_pos[i] = s;     // log(positive_sim) = s
            }
        }
    }

    // Reduce rs across the 16-lane tx group (lanes are 16-aligned in-warp).
    #pragma unroll
    for (int ii = 0; ii < 4; ii++) {
        float v = rs[ii];
        v += __shfl_xor_sync(0xffffffffu, v, 8);
        v += __shfl_xor_sync(0xffffffffu, v, 4);
        v += __shfl_xor_sync(0xffffffffu, v, 2);
        v += __shfl_xor_sync(0xffffffffu, v, 1);
        if (tx == 0) atomicAdd(&g_rowsum[i0 + ty * 4 + ii], v);
    }
}

// ---------------------------------------------------------------------------
// Kernel 3: loss_i = log(rowsum_i) - s_pos_i ; mean over all rows.
// ---------------------------------------------------------------------------
__global__ void final_kernel(float* __restrict__ out) {
    int tid = threadIdx.x;  // 512 threads
    float sum = 0.0f;
    for (int i = tid; i < N_ROWS; i += 512)
        sum += logf(g_rowsum[i]) - g_pos[i];
    #pragma unroll
    for (int m = 16; m; m >>= 1) sum += __shfl_xor_sync(0xffffffffu, sum, m);
    __shared__ float sh[16];
    if ((tid & 31) == 0) sh[tid >> 5] = sum;
    __syncthreads();
    if (tid < 32) {
        float v = (tid < 16) ? sh[tid] : 0.0f;
        #pragma unroll
        for (int m = 8; m; m >>= 1) v += __shfl_xor_sync(0xffffffffu, v, m);
        if (tid == 0) out[0] = v * (1.0f / N_ROWS);
    }
}

// ---------------------------------------------------------------------------
extern "C" void kernel_launch(void* const* d_in, const int* in_sizes, int n_in,
                              void* d_out, int out_size) {
    const float* zi = (const float*)d_in[0];
    const float* zj = (const float*)d_in[1];
    float* out = (float*)d_out;

    normalize_kernel<<<N_ROWS, 64>>>(zi, zj);
    sim_kernel<<<dim3(64, 4), 256>>>();
    final_kernel<<<1, 512>>>(out);
}

// round 4
// speedup vs baseline: 11.4179x; 11.4179x over previous
#include <cuda_runtime.h>
#include <cuda_bf16.h>
#include <cstdint>
#include <math.h>

#define B_ROWS 2048
#define N_TOT  4096
#define DIM    256
#define SCALE  2.0f        // 1/TEMPERATURE
#define TM 128
#define TN 128
#define KC 64              // k-chunk
#define NKC (DIM / KC)     // 4
#define PAD_BF16 8
#define ROWB ((KC + PAD_BF16) * 2)       // 144 B smem row stride
#define ABUF_B (TM * ROWB)               // 18432
#define BBUF_B (TN * ROWB)               // 18432
#define SMEM_DYN (2 * (ABUF_B + BBUF_B)) // 73728

__device__ __nv_bfloat16 g_zb[N_TOT * DIM];   // normalized rows (bf16), 2MB
__device__ float g_rowsum[N_TOT];
__device__ float g_pos[N_TOT];

// ---------------------------------------------------------------- helpers ---
__device__ __forceinline__ uint32_t smem_u32(const void* p) {
    uint32_t a;
    asm("{ .reg .u64 t; cvta.to.shared.u64 t, %1; cvt.u32.u64 %0, t; }" : "=r"(a) : "l"(p));
    return a;
}
__device__ __forceinline__ void cp_async16(uint32_t dst, const void* src) {
    asm volatile("cp.async.cg.shared.global [%0], [%1], 16;" :: "r"(dst), "l"(src));
}
__device__ __forceinline__ void cp_commit() {
    asm volatile("cp.async.commit_group;");
}
template <int N>
__device__ __forceinline__ void cp_wait() {
    asm volatile("cp.async.wait_group %0;" :: "n"(N));
}
__device__ __forceinline__ void ldmatrix4(uint32_t* r, uint32_t addr) {
    asm volatile("ldmatrix.sync.aligned.m8n8.x4.shared.b16 {%0,%1,%2,%3}, [%4];"
                 : "=r"(r[0]), "=r"(r[1]), "=r"(r[2]), "=r"(r[3]) : "r"(addr));
}
__device__ __forceinline__ void mma16816(float* c, const uint32_t* a, uint32_t b0, uint32_t b1) {
    asm volatile(
        "mma.sync.aligned.m16n8k16.row.col.f32.bf16.bf16.f32 "
        "{%0,%1,%2,%3}, {%4,%5,%6,%7}, {%8,%9}, {%0,%1,%2,%3};"
        : "+f"(c[0]), "+f"(c[1]), "+f"(c[2]), "+f"(c[3])
        : "r"(a[0]), "r"(a[1]), "r"(a[2]), "r"(a[3]), "r"(b0), "r"(b1));
}

// ------------------------------------------------------- normalize (bf16) ---
__global__ __launch_bounds__(256) void normalize_kernel(const float* __restrict__ zi,
                                                        const float* __restrict__ zj) {
    int row  = (blockIdx.x * 256 + threadIdx.x) >> 5;
    int lane = threadIdx.x & 31;
    const float* src = (row < B_ROWS) ? zi + (size_t)row * DIM
                                      : zj + (size_t)(row - B_ROWS) * DIM;
    float4 v0 = ((const float4*)src)[lane * 2];
    float4 v1 = ((const float4*)src)[lane * 2 + 1];
    float ss = v0.x*v0.x + v0.y*v0.y + v0.z*v0.z + v0.w*v0.w
             + v1.x*v1.x + v1.y*v1.y + v1.z*v1.z + v1.w*v1.w;
    #pragma unroll
    for (int m = 16; m; m >>= 1) ss += __shfl_xor_sync(0xffffffffu, ss, m);
    float inv = 1.0f / fmaxf(sqrtf(ss), 1e-12f);
    __nv_bfloat16 o[8];
    o[0] = __float2bfloat16(v0.x * inv); o[1] = __float2bfloat16(v0.y * inv);
    o[2] = __float2bfloat16(v0.z * inv); o[3] = __float2bfloat16(v0.w * inv);
    o[4] = __float2bfloat16(v1.x * inv); o[5] = __float2bfloat16(v1.y * inv);
    o[6] = __float2bfloat16(v1.z * inv); o[7] = __float2bfloat16(v1.w * inv);
    *(uint4*)(g_zb + (size_t)row * DIM + lane * 8) = *(const uint4*)o;
    if (lane == 0) g_rowsum[row] = 0.0f;
}

// ------------------------------------------------- fused sim via HMMA -------
extern __shared__ char dsm[];

__global__ __launch_bounds__(256, 2) void sim_mma_kernel() {
    __shared__ float s_row[TM];

    const int tid  = threadIdx.x;
    const int wid  = tid >> 5;
    const int lane = tid & 31;
    const int wm   = wid & 1;       // 0..1 : 64-row slab
    const int wn   = wid >> 1;      // 0..3 : 32-col slab
    const int i0   = blockIdx.x * TM;
    const int j0   = blockIdx.y * TN;

    const uint32_t base = smem_u32(dsm);
    // buffers: [buf][A|B]
    uint32_t Ab[2] = { base,                       base + ABUF_B + BBUF_B };
    uint32_t Bb[2] = { base + ABUF_B,              base + ABUF_B + BBUF_B + ABUF_B };

    // ---- cp.async stage of one k-chunk into buffer b
    auto prefetch = [&](int kc, int b) {
        const __nv_bfloat16* gA = g_zb + (size_t)i0 * DIM + kc * KC;
        const __nv_bfloat16* gB = g_zb + (size_t)j0 * DIM + kc * KC;
        #pragma unroll
        for (int it = 0; it < 4; it++) {           // 1024 ops / 256 thr
            int idx = it * 256 + tid;
            int row = idx >> 3, c8 = idx & 7;      // 8 x 16B per 128B row
            cp_async16(Ab[b] + row * ROWB + c8 * 16, gA + (size_t)row * DIM + c8 * 8);
        }
        #pragma unroll
        for (int it = 0; it < 4; it++) {
            int idx = it * 256 + tid;
            int row = idx >> 3, c8 = idx & 7;
            cp_async16(Bb[b] + row * ROWB + c8 * 16, gB + (size_t)row * DIM + c8 * 8);
        }
        cp_commit();
    };

    float c[4][4][4] = {};   // [mt][nt][e]

    prefetch(0, 0);

    for (int kc = 0; kc < NKC; kc++) {
        if (kc + 1 < NKC) prefetch(kc + 1, (kc + 1) & 1);
        if (kc + 1 < NKC) cp_wait<1>(); else cp_wait<0>();
        __syncthreads();

        const uint32_t A = Ab[kc & 1];
        const uint32_t B = Bb[kc & 1];
        const int lr = lane & 15, lh = lane >> 4;

        #pragma unroll
        for (int ks = 0; ks < KC / 16; ks++) {     // 4 k16 steps
            const uint32_t koff = ks * 32 + lh * 16;
            uint32_t af[4][4], bf[2][4];
            #pragma unroll
            for (int mt = 0; mt < 4; mt++)
                ldmatrix4(af[mt], A + (wm * 64 + mt * 16 + lr) * ROWB + koff);
            #pragma unroll
            for (int n2 = 0; n2 < 2; n2++)
                ldmatrix4(bf[n2], B + (wn * 32 + n2 * 16 + lr) * ROWB + koff);
            #pragma unroll
            for (int mt = 0; mt < 4; mt++)
                #pragma unroll
                for (int nt = 0; nt < 4; nt++)
                    mma16816(c[mt][nt], af[mt], bf[nt >> 1][nt & 1], bf[nt >> 1][(nt & 1) + 2]);
        }
        __syncthreads();   // all reads done before this buffer is re-filled
    }

    // ---- epilogue: exp, diag exclusion, positive capture, row reduction ----
    if (tid < TM) s_row[tid] = 0.0f;
    __syncthreads();

    const int grp = lane >> 2, tig = lane & 3;
    float rs[8] = {};   // [mt*2 + rhalf]

    #pragma unroll
    for (int mt = 0; mt < 4; mt++) {
        #pragma unroll
        for (int rh = 0; rh < 2; rh++) {
            const int i    = i0 + wm * 64 + mt * 16 + grp + rh * 8;
            const int posj = (i + B_ROWS) & (N_TOT - 1);
            float acc = 0.0f;
            #pragma unroll
            for (int nt = 0; nt < 4; nt++) {
                #pragma unroll
                for (int cb = 0; cb < 2; cb++) {
                    const int j   = j0 + wn * 32 + nt * 8 + tig * 2 + cb;
                    const float s = SCALE * c[mt][nt][rh * 2 + cb];
                    const float e = __expf(s);
                    if (j != i)    acc += e;
                    if (j == posj) g_pos[i] = s;
                }
            }
            rs[mt * 2 + rh] = acc;
        }
    }
    // reduce across tig (lanes sharing same rows differ in bits 0-1)
    #pragma unroll
    for (int r = 0; r < 8; r++) {
        rs[r] += __shfl_xor_sync(0xffffffffu, rs[r], 1);
        rs[r] += __shfl_xor_sync(0xffffffffu, rs[r], 2);
    }
    if (tig == 0) {
        #pragma unroll
        for (int r = 0; r < 8; r++) {
            int row_local = wm * 64 + (r >> 1) * 16 + grp + (r & 1) * 8;
            atomicAdd(&s_row[row_local], rs[r]);
        }
    }
    __syncthreads();
    if (tid < TM) atomicAdd(&g_rowsum[i0 + tid], s_row[tid]);
}

// ----------------------------------------------------------------- reduce ---
__global__ void final_kernel(float* __restrict__ out) {
    int tid = threadIdx.x;  // 512
    float sum = 0.0f;
    for (int i = tid; i < N_TOT; i += 512)
        sum += logf(g_rowsum[i]) - g_pos[i];
    #pragma unroll
    for (int m = 16; m; m >>= 1) sum += __shfl_xor_sync(0xffffffffu, sum, m);
    __shared__ float sh[16];
    if ((tid & 31) == 0) sh[tid >> 5] = sum;
    __syncthreads();
    if (tid < 32) {
        float v = (tid < 16) ? sh[tid] : 0.0f;
        #pragma unroll
        for (int m = 8; m; m >>= 1) v += __shfl_xor_sync(0xffffffffu, v, m);
        if (tid == 0) out[0] = v * (1.0f / N_TOT);
    }
}

// ---------------------------------------------------------------------------
extern "C" void kernel_launch(void* const* d_in, const int* in_sizes, int n_in,
                              void* d_out, int out_size) {
    const float* zi = (const float*)d_in[0];
    const float* zj = (const float*)d_in[1];
    float* out = (float*)d_out;

    cudaFuncSetAttribute(sim_mma_kernel,
                         cudaFuncAttributeMaxDynamicSharedMemorySize, SMEM_DYN);

    normalize_kernel<<<N_TOT / 8, 256>>>(zi, zj);
    sim_mma_kernel<<<dim3(N_TOT / TM, N_TOT / TN), 256, SMEM_DYN>>>();
    final_kernel<<<1, 512>>>(out);
}

// round 7
// speedup vs baseline: 13.9828x; 1.2246x over previous
#include <cuda_runtime.h>
#include <cuda_bf16.h>
#include <cstdint>
#include <math.h>

#define B_ROWS 2048
#define N_TOT  4096
#define DIM    256
#define SCALE  2.0f        // 1/TEMPERATURE
#define TM 128
#define TN 128
#define KC 64
#define NKC (DIM / KC)
#define PAD_BF16 8
#define ROWB ((KC + PAD_BF16) * 2)       // 144 B smem row stride
#define ABUF_B (TM * ROWB)
#define BBUF_B (TN * ROWB)
#define SMEM_DYN (2 * (ABUF_B + BBUF_B)) // 73728
#define NTILE (N_TOT / TM)               // 32
#define NBLK  (NTILE * (NTILE + 1) / 2)  // 528 triangular tiles

__device__ __nv_bfloat16 g_zb[N_TOT * DIM];
__device__ float g_rowsum[N_TOT];
__device__ float g_pos[N_TOT];
__device__ unsigned int g_count;

// ---------------------------------------------------------------- helpers ---
__device__ __forceinline__ uint32_t smem_u32(const void* p) {
    uint32_t a;
    asm("{ .reg .u64 t; cvta.to.shared.u64 t, %1; cvt.u32.u64 %0, t; }" : "=r"(a) : "l"(p));
    return a;
}
__device__ __forceinline__ void cp_async16(uint32_t dst, const void* src) {
    asm volatile("cp.async.cg.shared.global [%0], [%1], 16;" :: "r"(dst), "l"(src));
}
__device__ __forceinline__ void cp_commit() { asm volatile("cp.async.commit_group;"); }
template <int N>
__device__ __forceinline__ void cp_wait() {
    asm volatile("cp.async.wait_group %0;" :: "n"(N));
}
__device__ __forceinline__ void ldmatrix4(uint32_t* r, uint32_t addr) {
    asm volatile("ldmatrix.sync.aligned.m8n8.x4.shared.b16 {%0,%1,%2,%3}, [%4];"
                 : "=r"(r[0]), "=r"(r[1]), "=r"(r[2]), "=r"(r[3]) : "r"(addr));
}
__device__ __forceinline__ void mma16816(float* c, const uint32_t* a, uint32_t b0, uint32_t b1) {
    asm volatile(
        "mma.sync.aligned.m16n8k16.row.col.f32.bf16.bf16.f32 "
        "{%0,%1,%2,%3}, {%4,%5,%6,%7}, {%8,%9}, {%0,%1,%2,%3};"
        : "+f"(c[0]), "+f"(c[1]), "+f"(c[2]), "+f"(c[3])
        : "r"(a[0]), "r"(a[1]), "r"(a[2]), "r"(a[3]), "r"(b0), "r"(b1));
}

// ------------------------------------------------------- normalize (bf16) ---
// 16 lanes per row (2 rows/warp), MLP=4. Grid: N_TOT/16 = 256 blocks.
__global__ __launch_bounds__(256) void normalize_kernel(const float* __restrict__ zi,
                                                        const float* __restrict__ zj) {
    const int warp = (blockIdx.x * 256 + threadIdx.x) >> 5;
    const int lane = threadIdx.x & 31;
    const int l    = lane & 15;
    const int row  = warp * 2 + (lane >> 4);   // 2048 warps x 2 rows = 4096
    const float* src = (row < B_ROWS) ? zi + (size_t)row * DIM
                                      : zj + (size_t)(row - B_ROWS) * DIM;
    float4 v[4];
    #pragma unroll
    for (int t = 0; t < 4; t++) v[t] = ((const float4*)src)[l * 4 + t];

    float ss = 0.0f;
    #pragma unroll
    for (int t = 0; t < 4; t++)
        ss += v[t].x*v[t].x + v[t].y*v[t].y + v[t].z*v[t].z + v[t].w*v[t].w;
    #pragma unroll
    for (int m = 8; m; m >>= 1) ss += __shfl_xor_sync(0xffffffffu, ss, m);
    const float inv = 1.0f / fmaxf(sqrtf(ss), 1e-12f);

    __nv_bfloat16 o[16];
    #pragma unroll
    for (int t = 0; t < 4; t++) {
        o[t*4+0] = __float2bfloat16(v[t].x * inv);
        o[t*4+1] = __float2bfloat16(v[t].y * inv);
        o[t*4+2] = __float2bfloat16(v[t].z * inv);
        o[t*4+3] = __float2bfloat16(v[t].w * inv);
    }
    uint4* dst = (uint4*)(g_zb + (size_t)row * DIM + l * 16);
    dst[0] = ((const uint4*)o)[0];
    dst[1] = ((const uint4*)o)[1];

    if (l == 0) g_rowsum[row] = 0.0f;
    if (blockIdx.x == 0 && threadIdx.x == 0) g_count = 0u;
}

// -------------------- fused sim via HMMA, triangular tiles, fused reduce ----
extern __shared__ char dsm[];

__global__ __launch_bounds__(256, 2) void sim_mma_kernel(float* __restrict__ out) {
    __shared__ float s_row[TM];
    __shared__ float s_col[TN];
    __shared__ int   s_last;

    const int tid  = threadIdx.x;
    const int wid  = tid >> 5;
    const int lane = tid & 31;
    const int wm   = wid & 1;
    const int wn   = wid >> 1;

    // triangular decode: bi <= bj
    int t = blockIdx.x, bi = 0;
    while (t >= NTILE - bi) { t -= NTILE - bi; bi++; }
    const int bj   = bi + t;
    const bool diag = (bi == bj);
    const int i0 = bi * TM;
    const int j0 = bj * TN;

    const uint32_t base = smem_u32(dsm);
    uint32_t Ab[2] = { base,          base + ABUF_B + BBUF_B };
    uint32_t Bb[2] = { base + ABUF_B, base + ABUF_B + BBUF_B + ABUF_B };
    if (diag) { Bb[0] = Ab[0]; Bb[1] = Ab[1]; }   // A tile == B tile

    auto prefetch = [&](int kc, int b) {
        const __nv_bfloat16* gA = g_zb + (size_t)i0 * DIM + kc * KC;
        #pragma unroll
        for (int it = 0; it < 4; it++) {
            int idx = it * 256 + tid;
            int row = idx >> 3, c8 = idx & 7;
            cp_async16(Ab[b] + row * ROWB + c8 * 16, gA + (size_t)row * DIM + c8 * 8);
        }
        if (!diag) {
            const __nv_bfloat16* gB = g_zb + (size_t)j0 * DIM + kc * KC;
            #pragma unroll
            for (int it = 0; it < 4; it++) {
                int idx = it * 256 + tid;
                int row = idx >> 3, c8 = idx & 7;
                cp_async16(Bb[b] + row * ROWB + c8 * 16, gB + (size_t)row * DIM + c8 * 8);
            }
        }
        cp_commit();
    };

    float c[4][4][4] = {};
    prefetch(0, 0);

    for (int kc = 0; kc < NKC; kc++) {
        if (kc + 1 < NKC) prefetch(kc + 1, (kc + 1) & 1);
        if (kc + 1 < NKC) cp_wait<1>(); else cp_wait<0>();
        __syncthreads();

        const uint32_t A = Ab[kc & 1];
        const uint32_t B = Bb[kc & 1];
        const int lr = lane & 15, lh = lane >> 4;

        #pragma unroll
        for (int ks = 0; ks < KC / 16; ks++) {
            const uint32_t koff = ks * 32 + lh * 16;
            uint32_t af[4][4], bf[2][4];
            #pragma unroll
            for (int mt = 0; mt < 4; mt++)
                ldmatrix4(af[mt], A + (wm * 64 + mt * 16 + lr) * ROWB + koff);
            #pragma unroll
            for (int n2 = 0; n2 < 2; n2++)
                ldmatrix4(bf[n2], B + (wn * 32 + n2 * 16 + lr) * ROWB + koff);
            #pragma unroll
            for (int mt = 0; mt < 4; mt++)
                #pragma unroll
                for (int nt = 0; nt < 4; nt++)
                    mma16816(c[mt][nt], af[mt], bf[nt >> 1][nt & 1], bf[nt >> 1][(nt & 1) + 2]);
        }
        __syncthreads();
    }

    // ---- epilogue: exp once; row sums (i) + mirrored col sums (j) ----------
    if (tid < TM) { s_row[tid] = 0.0f; s_col[tid] = 0.0f; }
    __syncthreads();

    const int grp = lane >> 2, tig = lane & 3;
    float rs[8] = {}, cs[8] = {};

    #pragma unroll
    for (int mt = 0; mt < 4; mt++) {
        #pragma unroll
        for (int rh = 0; rh < 2; rh++) {
            const int i    = i0 + wm * 64 + mt * 16 + grp + rh * 8;
            const int posj = (i + B_ROWS) & (N_TOT - 1);
            #pragma unroll
            for (int nt = 0; nt < 4; nt++) {
                #pragma unroll
                for (int cb = 0; cb < 2; cb++) {
                    const int j   = j0 + wn * 32 + nt * 8 + tig * 2 + cb;
                    const float s = SCALE * c[mt][nt][rh * 2 + cb];
                    const float e = __expf(s);
                    if (!diag) {
                        rs[mt * 2 + rh] += e;
                        cs[nt * 2 + cb] += e;
                        if (j == posj) { g_pos[i] = s; g_pos[j] = s; }
                    } else if (j != i) {
                        rs[mt * 2 + rh] += e;
                    }
                }
            }
        }
    }
    // row sums: reduce across tig (lane bits 0-1)
    #pragma unroll
    for (int r = 0; r < 8; r++) {
        rs[r] += __shfl_xor_sync(0xffffffffu, rs[r], 1);
        rs[r] += __shfl_xor_sync(0xffffffffu, rs[r], 2);
    }
    if (tig == 0) {
        #pragma unroll
        for (int r = 0; r < 8; r++)
            atomicAdd(&s_row[wm * 64 + (r >> 1) * 16 + grp + (r & 1) * 8], rs[r]);
    }
    // col sums: reduce across grp (lane bits 2-4)
    if (!diag) {
        #pragma unroll
        for (int r = 0; r < 8; r++) {
            cs[r] += __shfl_xor_sync(0xffffffffu, cs[r], 4);
            cs[r] += __shfl_xor_sync(0xffffffffu, cs[r], 8);
            cs[r] += __shfl_xor_sync(0xffffffffu, cs[r], 16);
        }
        if (grp == 0) {
            #pragma unroll
            for (int r = 0; r < 8; r++)
                atomicAdd(&s_col[wn * 32 + (r >> 1) * 8 + tig * 2 + (r & 1)], cs[r]);
        }
    }
    __syncthreads();
    if (tid < TM) {
        atomicAdd(&g_rowsum[i0 + tid], s_row[tid]);
        if (!diag) atomicAdd(&g_rowsum[j0 + tid], s_col[tid]);
    }

    // ---- last CTA computes the loss ----------------------------------------
    __threadfence();
    if (tid == 0) s_last = (atomicAdd(&g_count, 1u) == (unsigned)(gridDim.x - 1));
    __syncthreads();
    if (s_last) {
        float sum = 0.0f;
        for (int i = tid; i < N_TOT; i += 256)
            sum += logf(__ldcg(&g_rowsum[i])) - __ldcg(&g_pos[i]);
        #pragma unroll
        for (int m = 16; m; m >>= 1) sum += __shfl_xor_sync(0xffffffffu, sum, m);
        __shared__ float sh[8];
        if (lane == 0) sh[wid] = sum;
        __syncthreads();
        if (tid < 32) {
            float v = (tid < 8) ? sh[tid] : 0.0f;
            #pragma unroll
            for (int m = 4; m; m >>= 1) v += __shfl_xor_sync(0xffffffffu, v, m);
            if (tid == 0) out[0] = v * (1.0f / N_TOT);
        }
    }
}

// ---------------------------------------------------------------------------
extern "C" void kernel_launch(void* const* d_in, const int* in_sizes, int n_in,
                              void* d_out, int out_size) {
    const float* zi = (const float*)d_in[0];
    const float* zj = (const float*)d_in[1];
    float* out = (float*)d_out;

    cudaFuncSetAttribute(sim_mma_kernel,
                         cudaFuncAttributeMaxDynamicSharedMemorySize, SMEM_DYN);

    normalize_kernel<<<N_TOT / 16, 256>>>(zi, zj);
    sim_mma_kernel<<<NBLK, 256, SMEM_DYN>>>(out);
}